// round 12
// baseline (speedup 1.0000x reference)
#include <cuda_runtime.h>
#include <cuda_fp16.h>
#include <cstdint>

#define N_OBJn 512
#define C_OBJn 151
#define N_RELn 16384
#define C_RELn 51
#define D_DIM  4096

#define OUT_PREDS  (N_OBJn * C_OBJn)          /* 77312 */
#define OUT_REL    (OUT_PREDS + N_OBJn)       /* 77824 */

// Scratch (device globals — no allocation allowed)
__device__ float g_probsT[C_OBJn * N_OBJn];   // [class][obj]
__device__ float g_maskedT[C_OBJn * N_OBJn];  // [class][obj], class 0 unused
// W as fp16, pre-swizzled per 64-col chunk tile: 64 tiles x (64 rows x 128B)
__device__ __align__(16) unsigned char g_Wsw[64 * 8192];

// ---------------------------------------------------------------------------
// helpers
// ---------------------------------------------------------------------------
__device__ __forceinline__ uint32_t smem_u32(const void* p) {
    uint32_t a;
    asm("{ .reg .u64 t; cvta.to.shared.u64 t, %1; cvt.u32.u64 %0, t; }" : "=r"(a) : "l"(p));
    return a;
}
#define SW128(o) ((o) ^ (((o) >> 3) & 0x70))

__device__ __forceinline__ void cp_async16(uint32_t dst, const void* src) {
    asm volatile("cp.async.cg.shared.global [%0], [%1], 16;" :: "r"(dst), "l"(src));
}
#define CP_COMMIT() asm volatile("cp.async.commit_group;")
#define CP_WAIT2()  asm volatile("cp.async.wait_group 2;")

__device__ __forceinline__ void ldmx4(uint32_t* r, uint32_t addr) {
    asm volatile("ldmatrix.sync.aligned.m8n8.x4.shared.b16 {%0,%1,%2,%3}, [%4];"
                 : "=r"(r[0]), "=r"(r[1]), "=r"(r[2]), "=r"(r[3]) : "r"(addr));
}
__device__ __forceinline__ void mma_f16(float* d, const uint32_t* a, const uint32_t* b) {
    asm volatile(
        "mma.sync.aligned.m16n8k16.row.col.f32.f16.f16.f32 "
        "{%0,%1,%2,%3},{%4,%5,%6,%7},{%8,%9},{%0,%1,%2,%3};"
        : "+f"(d[0]), "+f"(d[1]), "+f"(d[2]), "+f"(d[3])
        : "r"(a[0]), "r"(a[1]), "r"(a[2]), "r"(a[3]), "r"(b[0]), "r"(b[1]));
}

// Exact IoU>0.3 predicate, division-free fast path (proven r9, byte-identical).
__device__ __forceinline__ bool iou_gt(float inter, float den) {
    float t    = __fmul_rn(0.3f, den);
    float diff = __fsub_rn(inter, t);
    bool pred  = diff > 0.0f;
    if (fabsf(diff) < __fmul_rn(t, 4e-7f))
        pred = __fdiv_rn(inter, den) > 0.3f;
    return pred;
}

__device__ __forceinline__ float iou_inter(const float4& a, const float4& b) {
    float xx1 = fmaxf(a.x, b.x);
    float yy1 = fmaxf(a.y, b.y);
    float xx2 = fminf(a.z, b.z);
    float yy2 = fminf(a.w, b.w);
    float wd = fmaxf(__fadd_rn(__fsub_rn(xx2, xx1), 1.0f), 0.0f);
    float ht = fmaxf(__fadd_rn(__fsub_rn(yy2, yy1), 1.0f), 0.0f);
    return __fmul_rn(wd, ht);
}

// ---------------------------------------------------------------------------
// Kernel 1: row softmax (one warp per row) + copy logits to out[0:77312)
// ---------------------------------------------------------------------------
__global__ void softmax_copy_kernel(const float* __restrict__ logits,
                                    float* __restrict__ out)
{
    int warp = threadIdx.x >> 5;
    int lane = threadIdx.x & 31;
    int row  = blockIdx.x * 8 + warp;
    if (row >= N_OBJn) return;

    float v[5];
    float mx = -1e30f;
#pragma unroll
    for (int s = 0; s < 5; s++) {
        int c = lane + 32 * s;
        v[s] = (c < C_OBJn) ? logits[row * C_OBJn + c] : -1e30f;
        mx = fmaxf(mx, v[s]);
    }
#pragma unroll
    for (int o = 16; o; o >>= 1) mx = fmaxf(mx, __shfl_xor_sync(0xffffffffu, mx, o));

    float e[5];
    float sum = 0.f;
#pragma unroll
    for (int s = 0; s < 5; s++) {
        int c = lane + 32 * s;
        e[s] = (c < C_OBJn) ? expf(v[s] - mx) : 0.f;
        sum += e[s];
    }
#pragma unroll
    for (int o = 16; o; o >>= 1) sum += __shfl_xor_sync(0xffffffffu, sum, o);

#pragma unroll
    for (int s = 0; s < 5; s++) {
        int c = lane + 32 * s;
        if (c < C_OBJn) {
            g_probsT[c * N_OBJn + row] = __fdiv_rn(e[s], sum);
            out[row * C_OBJn + c] = v[s];   // obj_dists2 passthrough
        }
    }
}

// ---------------------------------------------------------------------------
// Kernel 2: argmax, one WARP per object (first-max tie: smaller class wins)
// ---------------------------------------------------------------------------
__global__ void argmax_kernel(float* __restrict__ out)
{
    int wid  = threadIdx.x >> 5;
    int lane = threadIdx.x & 31;
    int obj  = blockIdx.x * 8 + wid;
    if (obj >= N_OBJn) return;

    float bv = -1.0f;
    int   bc = 1000;
#pragma unroll
    for (int s = 0; s < 5; s++) {
        int c = 1 + lane + 32 * s;
        if (c < C_OBJn) {
            float v = g_maskedT[c * N_OBJn + obj];
            if (v > bv || (v == bv && c < bc)) { bv = v; bc = c; }
        }
    }
#pragma unroll
    for (int o = 16; o; o >>= 1) {
        float ov = __shfl_xor_sync(0xffffffffu, bv, o);
        int   oc = __shfl_xor_sync(0xffffffffu, bc, o);
        if (ov > bv || (ov == bv && oc < bc)) { bv = ov; bc = oc; }
    }
    if (lane == 0) out[OUT_PREDS + obj] = (float)bc;
}

// ---------------------------------------------------------------------------
// Kernel 3: W fp32 -> fp16 pre-swizzled tiles; split in halves so the fused
// kernel lands at ncu issue position 3. base = element offset.
// ---------------------------------------------------------------------------
__global__ void wsplit_kernel(const float* __restrict__ W, int base)
{
    int i = base + blockIdx.x * blockDim.x + threadIdx.x;   // n*4096 + k
    if (i >= 64 * D_DIM) return;
    int n = i >> 12;
    int k = i & 4095;
    float x = (n < C_RELn) ? W[i] : 0.0f;
    __half h = __float2half_rn(x);
    int chunk = k >> 6, kin = k & 63;
    uint32_t off = (uint32_t)(n * 128 + kin * 2);
    uint32_t dst = (uint32_t)chunk * 8192u + (off ^ ((uint32_t)(n & 7) * 16u));
    *(__half*)(g_Wsw + dst) = h;
}

// ---------------------------------------------------------------------------
// Kernel 4: FUSED NMS + GEMM, one launch, grid 406.
//   bid<300 && odd  -> NMS CTA, cls = (bid>>1)+1       (150 CTAs)
//   else            -> GEMM CTA, gemmId interleaved     (256 CTAs)
// Overlap rationale: NMS is ALU/issue-bound (DRAM 0.2%), GEMM is DRAM-bound
// (issue 23%) — co-resident CTAs use complementary pipes.
// GEMM: 512 threads, 4x4 warp grid of 16x16 tiles; identical (chunk, kk)
// accumulation order to r11 => bit-identical rel_err.
// ---------------------------------------------------------------------------
#define ASTRIDE 272
#define A_STAGE_B (64 * ASTRIDE)                       /* 17408 */
#define W_STAGE_B 8192
#define STAGE_B   (A_STAGE_B + W_STAGE_B)              /* 25600 */
#define OFF_STA(s) ((s) * STAGE_B)
#define OFF_STW(s) ((s) * STAGE_B + A_STAGE_B)
#define OFF_FB(b)  (3 * STAGE_B + (b) * 8192)
#define SM_TOTAL_G (3 * STAGE_B + 2 * 8192)            /* 93184 */

__global__ __launch_bounds__(512, 2) void fused_nms_gemm_kernel(
    const float* __restrict__ A, const float* __restrict__ bias,
    const float* __restrict__ boxes, float* __restrict__ out)
{
    extern __shared__ char smem[];
    const int bid  = blockIdx.x;
    const int tid  = threadIdx.x;
    const int lane = tid & 31;
    const int w    = tid >> 5;

    if (bid < 300 && (bid & 1)) {
        // ================= NMS path (logic unchanged from r10/r11) =========
        const int cls = (bid >> 1) + 1;
        unsigned long long* s_key = (unsigned long long*)smem;          // 4KB
        float4*   s_box  = (float4*)(smem + 4096);                      // 8KB
        float*    s_ar   = (float*)(smem + 12288);                      // 2KB
        unsigned* s_diag = (unsigned*)(smem + 14336);
        unsigned* s_sup  = (unsigned*)(smem + 14464);
        unsigned* s_keep = (unsigned*)(smem + 14528);

        {
            unsigned sb = __float_as_uint(g_probsT[cls * N_OBJn + tid]);
            s_key[tid] = ((unsigned long long)(~sb) << 32) | (unsigned)tid;
        }
        if (tid < 16) s_sup[tid] = 0u;
        __syncthreads();

        for (int k = 2; k <= 512; k <<= 1) {
            for (int j = k >> 1; j > 0; j >>= 1) {
                int ixj = tid ^ j;
                if (ixj > tid) {
                    unsigned long long a = s_key[tid], b = s_key[ixj];
                    bool up = ((tid & k) == 0);
                    if ((a > b) == up) { s_key[tid] = b; s_key[ixj] = a; }
                }
                __syncthreads();
            }
        }

        float4 cb;
        float  ca;
        {
            int o = (int)(s_key[tid] & 0x1FFu);
            cb = *(const float4*)&boxes[(o * C_OBJn + cls) * 4];
            ca = __fmul_rn(__fadd_rn(__fsub_rn(cb.z, cb.x), 1.0f),
                           __fadd_rn(__fsub_rn(cb.w, cb.y), 1.0f));
            s_box[tid] = cb;
            s_ar[tid]  = ca;
        }
        __syncthreads();

        unsigned supbit = 0;

#pragma unroll 1
        for (int B = 0; B < 16; B++) {
            {
                float4 db = s_box[(B << 5) + lane];
                float  da = s_ar[(B << 5) + lane];
#pragma unroll
                for (int rr = 0; rr < 2; rr++) {
                    int r = (B << 5) + (w << 1) + rr;
                    float4 rb = s_box[r];
                    float  ra = s_ar[r];
                    float inter = iou_inter(rb, db);
                    float den = __fsub_rn(__fadd_rn(ra, da), inter);
                    unsigned m = __ballot_sync(0xffffffffu, iou_gt(inter, den));
                    if (lane == 0) s_diag[(w << 1) + rr] = m;
                }
            }
            __syncthreads();

            unsigned cur = s_sup[B];
            unsigned kb  = 0;
#pragma unroll
            for (int t = 0; t < 32; t++) {
                unsigned mi   = s_diag[t];
                unsigned keep = ((cur >> t) & 1u) ^ 1u;
                kb  |= keep << t;
                cur |= keep ? mi : 0u;
            }
            if (tid == 0) s_keep[B] = kb;

            if (w > B) {
                if (!supbit) {
                    unsigned bits = kb;
                    while (bits) {
                        int t = __ffs(bits) - 1;
                        bits &= bits - 1;
                        int i = (B << 5) + t;
                        float4 ib = s_box[i];
                        float  ia = s_ar[i];
                        float inter = iou_inter(ib, cb);
                        float den = __fsub_rn(__fadd_rn(ia, ca), inter);
                        if (iou_gt(inter, den)) { supbit = 1u; break; }
                    }
                }
                unsigned m = __ballot_sync(0xffffffffu, supbit);
                if (lane == 0 && B == w - 1) s_sup[w] = m;
            }
            __syncthreads();
        }

        {
            unsigned kb = s_keep[w];
            bool keep = (kb >> lane) & 1u;
            int o = (int)(s_key[tid] & 0x1FFu);
            float sc = __uint_as_float(~(unsigned)(s_key[tid] >> 32));
            g_maskedT[cls * N_OBJn + o] = keep ? sc : 0.0f;
        }
        return;
    }

    // ==================== GEMM path (512 threads, 4x4 warps) ===============
    const int gemmId = (bid < 300) ? (bid >> 1) : (150 + bid - 300);
    const uint32_t sb = smem_u32(smem);
    const int warp_n = w & 3;      // 16-col tile
    const int warp_m = w >> 2;     // 16-row tile
    const int rowBase = gemmId * 64;

    const int ar = tid >> 4;       // 0..31 base row; handles ar, ar+32
    const int aq = tid & 15;       // 16B quad in 256B k-window
    const float* aPtr = A + (size_t)(rowBase + ar) * D_DIM + aq * 4;

    auto issue = [&](int i) {       // one commit_group per call (maybe empty)
        if (i < 64) {
            uint32_t ab = sb + OFF_STA(i % 3);
            const float* ag = aPtr + i * 64;
#pragma unroll
            for (int p = 0; p < 2; p++)
                cp_async16(ab + (uint32_t)(ar + 32 * p) * ASTRIDE + aq * 16,
                           ag + (size_t)32 * p * D_DIM);
            uint32_t wb = sb + OFF_STW(i % 3);
            cp_async16(wb + tid * 16, g_Wsw + (size_t)i * 8192 + tid * 16);
        }
        CP_COMMIT();
    };

    float acc[2][4];
#pragma unroll
    for (int nt = 0; nt < 2; nt++)
#pragma unroll
        for (int e = 0; e < 4; e++) acc[nt][e] = 0.f;

    const uint32_t aRow = (uint32_t)(warp_m * 16 + (lane & 15)) * 128 + (uint32_t)(lane >> 4) * 16;
    const uint32_t bRow = (uint32_t)(warp_n * 16 + ((lane >> 4) & 1) * 8 + (lane & 7)) * 128 +
                          (uint32_t)((lane >> 3) & 1) * 16;

    issue(0); issue(1); issue(2);

#pragma unroll 1
    for (int i = 0; i < 64; i++) {
        CP_WAIT2();
        __syncthreads();                 // stage i visible to all

        const int s = i % 3;
        // convert A stage -> fp16 swizzled buffer (i&1)
        {
            const char* ap = smem + OFF_STA(s);
            char* fb = smem + OFF_FB(i & 1);
#pragma unroll
            for (int p = 0; p < 2; p++) {
                int r = ar + 32 * p;
                float4 v = *(const float4*)(ap + r * ASTRIDE + aq * 16);
                __half2 h01 = __floats2half2_rn(v.x, v.y);
                __half2 h23 = __floats2half2_rn(v.z, v.w);
                *(uint2*)(fb + SW128((uint32_t)(r * 128 + aq * 8))) =
                    make_uint2(*(uint32_t*)&h01, *(uint32_t*)&h23);
            }
        }
        // W fragments for the whole chunk into registers
        uint32_t bW[4][4];
        {
            uint32_t wb = sb + OFF_STW(s);
#pragma unroll
            for (int kk = 0; kk < 4; kk++)
                ldmx4(bW[kk], wb + SW128(bRow + (uint32_t)kk * 32));
        }
        __syncthreads();                 // fbuf ready; stage fully consumed

        issue(i + 3);                    // refill stage (i%3)

        const uint32_t fb = sb + OFF_FB(i & 1);
#pragma unroll
        for (int kk = 0; kk < 4; kk++) {
            uint32_t aH[4];
            ldmx4(aH, fb + SW128(aRow + (uint32_t)kk * 32));
            mma_f16(acc[0], aH, &bW[kk][0]);
            mma_f16(acc[1], aH, &bW[kk][2]);
        }
    }

    const int g  = lane >> 2;
    const int tg = lane & 3;
    int row0 = rowBase + warp_m * 16 + g;
#pragma unroll
    for (int nt = 0; nt < 2; nt++) {
        int col = warp_n * 16 + nt * 8 + tg * 2;
        if (col < C_RELn) {
            float b0 = bias[col];
            out[OUT_REL + (size_t)row0 * C_RELn + col]       = acc[nt][0] + b0;
            out[OUT_REL + (size_t)(row0 + 8) * C_RELn + col] = acc[nt][2] + b0;
        }
        if (col + 1 < C_RELn) {
            float b1 = bias[col + 1];
            out[OUT_REL + (size_t)row0 * C_RELn + col + 1]       = acc[nt][1] + b1;
            out[OUT_REL + (size_t)(row0 + 8) * C_RELn + col + 1] = acc[nt][3] + b1;
        }
    }
}

// ---------------------------------------------------------------------------
// Pipeline: wsplit halves (pos 0,1), softmax (pos 2), fused (pos 3), argmax.
// ---------------------------------------------------------------------------
extern "C" void kernel_launch(void* const* d_in, const int* in_sizes, int n_in,
                              void* d_out, int out_size)
{
    (void)in_sizes; (void)n_in; (void)out_size;
    const float* obj_logits = (const float*)d_in[0];
    const float* vr         = (const float*)d_in[1];
    const float* boxes      = (const float*)d_in[2];
    const float* W_vr       = (const float*)d_in[3];
    const float* b_vr       = (const float*)d_in[4];
    float* out = (float*)d_out;

    cudaFuncSetAttribute(fused_nms_gemm_kernel,
                         cudaFuncAttributeMaxDynamicSharedMemorySize, SM_TOTAL_G);

    wsplit_kernel<<<256, 512>>>(W_vr, 0);                            // pos 0
    wsplit_kernel<<<256, 512>>>(W_vr, 131072);                       // pos 1
    softmax_copy_kernel<<<64, 256>>>(obj_logits, out);               // pos 2
    fused_nms_gemm_kernel<<<406, 512, SM_TOTAL_G>>>(vr, b_vr, boxes, out); // pos 3
    argmax_kernel<<<64, 256>>>(out);                                 // pos 4
}

// round 13
// speedup vs baseline: 1.0161x; 1.0161x over previous
#include <cuda_runtime.h>
#include <cuda_fp16.h>
#include <cstdint>

#define N_OBJn 512
#define C_OBJn 151
#define N_RELn 16384
#define C_RELn 51
#define D_DIM  4096

#define OUT_PREDS  (N_OBJn * C_OBJn)          /* 77312 */
#define OUT_REL    (OUT_PREDS + N_OBJn)       /* 77824 */

// Scratch (device globals — no allocation allowed)
__device__ float g_probsT[C_OBJn * N_OBJn];   // [class][obj]
__device__ float g_maskedT[C_OBJn * N_OBJn];  // [class][obj], class 0 unused
// W as fp16, pre-swizzled per 64-col chunk tile: 64 tiles x (64 rows x 128B)
__device__ __align__(16) unsigned char g_Wsw[64 * 8192];

// ---------------------------------------------------------------------------
// helpers
// ---------------------------------------------------------------------------
__device__ __forceinline__ uint32_t smem_u32(const void* p) {
    uint32_t a;
    asm("{ .reg .u64 t; cvta.to.shared.u64 t, %1; cvt.u32.u64 %0, t; }" : "=r"(a) : "l"(p));
    return a;
}
#define SW128(o) ((o) ^ (((o) >> 3) & 0x70))

__device__ __forceinline__ void cp_async16(uint32_t dst, const void* src) {
    asm volatile("cp.async.cg.shared.global [%0], [%1], 16;" :: "r"(dst), "l"(src));
}
#define CP_COMMIT() asm volatile("cp.async.commit_group;")
#define CP_WAIT2()  asm volatile("cp.async.wait_group 2;")

__device__ __forceinline__ void ldmx4(uint32_t* r, uint32_t addr) {
    asm volatile("ldmatrix.sync.aligned.m8n8.x4.shared.b16 {%0,%1,%2,%3}, [%4];"
                 : "=r"(r[0]), "=r"(r[1]), "=r"(r[2]), "=r"(r[3]) : "r"(addr));
}
__device__ __forceinline__ void mma_f16(float* d, const uint32_t* a, const uint32_t* b) {
    asm volatile(
        "mma.sync.aligned.m16n8k16.row.col.f32.f16.f16.f32 "
        "{%0,%1,%2,%3},{%4,%5,%6,%7},{%8,%9},{%0,%1,%2,%3};"
        : "+f"(d[0]), "+f"(d[1]), "+f"(d[2]), "+f"(d[3])
        : "r"(a[0]), "r"(a[1]), "r"(a[2]), "r"(a[3]), "r"(b[0]), "r"(b[1]));
}

// Exact IoU>0.3 predicate, division-free fast path (proven r9, byte-identical).
__device__ __forceinline__ bool iou_gt(float inter, float den) {
    float t    = __fmul_rn(0.3f, den);
    float diff = __fsub_rn(inter, t);
    bool pred  = diff > 0.0f;
    if (fabsf(diff) < __fmul_rn(t, 4e-7f))
        pred = __fdiv_rn(inter, den) > 0.3f;
    return pred;
}

__device__ __forceinline__ float iou_inter(const float4& a, const float4& b) {
    float xx1 = fmaxf(a.x, b.x);
    float yy1 = fmaxf(a.y, b.y);
    float xx2 = fminf(a.z, b.z);
    float yy2 = fminf(a.w, b.w);
    float wd = fmaxf(__fadd_rn(__fsub_rn(xx2, xx1), 1.0f), 0.0f);
    float ht = fmaxf(__fadd_rn(__fsub_rn(yy2, yy1), 1.0f), 0.0f);
    return __fmul_rn(wd, ht);
}

// ---------------------------------------------------------------------------
// Kernel 1: row softmax (one warp per row) + copy logits to out[0:77312)
// ---------------------------------------------------------------------------
__global__ void softmax_copy_kernel(const float* __restrict__ logits,
                                    float* __restrict__ out)
{
    int warp = threadIdx.x >> 5;
    int lane = threadIdx.x & 31;
    int row  = blockIdx.x * 8 + warp;
    if (row >= N_OBJn) return;

    float v[5];
    float mx = -1e30f;
#pragma unroll
    for (int s = 0; s < 5; s++) {
        int c = lane + 32 * s;
        v[s] = (c < C_OBJn) ? logits[row * C_OBJn + c] : -1e30f;
        mx = fmaxf(mx, v[s]);
    }
#pragma unroll
    for (int o = 16; o; o >>= 1) mx = fmaxf(mx, __shfl_xor_sync(0xffffffffu, mx, o));

    float e[5];
    float sum = 0.f;
#pragma unroll
    for (int s = 0; s < 5; s++) {
        int c = lane + 32 * s;
        e[s] = (c < C_OBJn) ? expf(v[s] - mx) : 0.f;
        sum += e[s];
    }
#pragma unroll
    for (int o = 16; o; o >>= 1) sum += __shfl_xor_sync(0xffffffffu, sum, o);

#pragma unroll
    for (int s = 0; s < 5; s++) {
        int c = lane + 32 * s;
        if (c < C_OBJn) {
            g_probsT[c * N_OBJn + row] = __fdiv_rn(e[s], sum);
            out[row * C_OBJn + c] = v[s];   // obj_dists2 passthrough
        }
    }
}

// ---------------------------------------------------------------------------
// Kernel 2: per-class NMS v4.
//  - register-resident bitonic sort: j<=16 stages via shfl.bfly (no barrier),
//    j>=32 via smem exchange (20 barriers total vs 45)
//  - step 3 vectorized: 32 independent row-IoUs per block, hit-mask AND kb
//    (removes the dependent LDS->cmp->break chain; output identical)
// ---------------------------------------------------------------------------
__global__ __launch_bounds__(512) void nms_kernel(const float* __restrict__ boxes)
{
    __shared__ unsigned long long s_xch[512];
    __shared__ float4 s_box[512];
    __shared__ float  s_ar[512];
    __shared__ unsigned s_diag[32];
    __shared__ unsigned s_sup[16];
    __shared__ unsigned s_keep[16];

    const int tid  = threadIdx.x;
    const int lane = tid & 31;
    const int w    = tid >> 5;              // 16 warps
    const int cls  = blockIdx.x + 1;

    unsigned long long key;
    {
        unsigned sbits = __float_as_uint(g_probsT[cls * N_OBJn + tid]);  // >= 0
        key = ((unsigned long long)(~sbits) << 32) | (unsigned)tid;
    }
    if (tid < 16) s_sup[tid] = 0u;

    // Ascending bitonic sort, element in register. Order == score desc, idx asc.
    for (int k = 2; k <= 512; k <<= 1) {
        for (int j = k >> 1; j > 0; j >>= 1) {
            unsigned long long partner;
            if (j >= 32) {
                __syncthreads();            // protect buffer from prior reads
                s_xch[tid] = key;
                __syncthreads();
                partner = s_xch[tid ^ j];
            } else {
                partner = __shfl_xor_sync(0xffffffffu, key, j);
            }
            bool up      = ((tid & k) == 0);
            bool lower   = ((tid & j) == 0);
            bool takeMin = (up == lower);
            bool gt = key > partner;
            unsigned long long mn = gt ? partner : key;
            unsigned long long mx = gt ? key : partner;
            key = takeMin ? mn : mx;
        }
    }
    // thread tid now holds sorted element tid (keys unique via idx tiebreak)

    // Load boxes in sorted order; own column box stays in registers
    float4 cb;
    float  ca;
    {
        int o = (int)(key & 0x1FFu);
        cb = *(const float4*)&boxes[(o * C_OBJn + cls) * 4];
        ca = __fmul_rn(__fadd_rn(__fsub_rn(cb.z, cb.x), 1.0f),
                       __fadd_rn(__fsub_rn(cb.w, cb.y), 1.0f));
        s_box[tid] = cb;
        s_ar[tid]  = ca;
    }
    __syncthreads();

    unsigned supbit = 0;   // this thread's column suppressed-so-far flag

#pragma unroll 1
    for (int B = 0; B < 16; B++) {
        // (1) diag block: warp w computes rows 2w, 2w+1; col box hoisted per B
        {
            float4 db = s_box[(B << 5) + lane];
            float  da = s_ar[(B << 5) + lane];
#pragma unroll
            for (int rr = 0; rr < 2; rr++) {
                int r = (B << 5) + (w << 1) + rr;
                float4 rb = s_box[r];
                float  ra = s_ar[r];
                float inter = iou_inter(rb, db);
                float den = __fsub_rn(__fadd_rn(ra, da), inter);
                unsigned m = __ballot_sync(0xffffffffu, iou_gt(inter, den));
                if (lane == 0) s_diag[(w << 1) + rr] = m;
            }
        }
        __syncthreads();

        // (2) keep-chain, redundant per warp (pure ALU, fully unrolled)
        unsigned cur = s_sup[B];
        unsigned kb  = 0;
#pragma unroll
        for (int t = 0; t < 32; t++) {
            unsigned mi   = s_diag[t];
            unsigned keep = ((cur >> t) & 1u) ^ 1u;
            kb  |= keep << t;
            cur |= keep ? mi : 0u;
        }
        if (tid == 0) s_keep[B] = kb;

        // (3) vectorized: 32 independent row-IoUs, mask with kept bits.
        // Identical output: supbit = OR over kept rows of iou_gt (monotone).
        if (w > B) {
            if (!supbit) {
                unsigned hits = 0;
#pragma unroll 8
                for (int t = 0; t < 32; t++) {
                    int i = (B << 5) + t;
                    float4 ib = s_box[i];
                    float  ia = s_ar[i];
                    float inter = iou_inter(ib, cb);
                    float den = __fsub_rn(__fadd_rn(ia, ca), inter);
                    hits |= (iou_gt(inter, den) ? 1u : 0u) << t;
                }
                supbit = (hits & kb) ? 1u : 0u;
            }
            unsigned m = __ballot_sync(0xffffffffu, supbit);
            if (lane == 0 && B == w - 1) s_sup[w] = m;
        }
        __syncthreads();
    }

    {
        unsigned kb = s_keep[w];
        bool keep = (kb >> lane) & 1u;
        int o = (int)(key & 0x1FFu);
        float sc = __uint_as_float(~(unsigned)(key >> 32));
        g_maskedT[cls * N_OBJn + o] = keep ? sc : 0.0f;
    }
}

// ---------------------------------------------------------------------------
// Kernel 3: argmax, one WARP per object (first-max tie: smaller class wins)
// ---------------------------------------------------------------------------
__global__ void argmax_kernel(float* __restrict__ out)
{
    int wid  = threadIdx.x >> 5;
    int lane = threadIdx.x & 31;
    int obj  = blockIdx.x * 8 + wid;
    if (obj >= N_OBJn) return;

    float bv = -1.0f;
    int   bc = 1000;
#pragma unroll
    for (int s = 0; s < 5; s++) {
        int c = 1 + lane + 32 * s;
        if (c < C_OBJn) {
            float v = g_maskedT[c * N_OBJn + obj];
            if (v > bv || (v == bv && c < bc)) { bv = v; bc = c; }
        }
    }
#pragma unroll
    for (int o = 16; o; o >>= 1) {
        float ov = __shfl_xor_sync(0xffffffffu, bv, o);
        int   oc = __shfl_xor_sync(0xffffffffu, bc, o);
        if (ov > bv || (ov == bv && oc < bc)) { bv = ov; bc = oc; }
    }
    if (lane == 0) out[OUT_PREDS + obj] = (float)bc;
}

// ---------------------------------------------------------------------------
// Kernel 4a: W fp32 -> fp16 pre-swizzled per-chunk tiles (r11, proven)
// ---------------------------------------------------------------------------
__global__ void wsplit_kernel(const float* __restrict__ W)
{
    int i = blockIdx.x * blockDim.x + threadIdx.x;   // n*4096 + k
    if (i >= 64 * D_DIM) return;
    int n = i >> 12;
    int k = i & 4095;
    float x = (n < C_RELn) ? W[i] : 0.0f;
    __half h = __float2half_rn(x);
    int chunk = k >> 6, kin = k & 63;
    uint32_t off = (uint32_t)(n * 128 + kin * 2);
    uint32_t dst = (uint32_t)chunk * 8192u + (off ^ ((uint32_t)(n & 7) * 16u));
    *(__half*)(g_Wsw + dst) = h;
}

// ---------------------------------------------------------------------------
// Kernel 4b: fp16 GEMM, 3-stage cp.async pipeline (UNCHANGED from r11: 66us)
// ---------------------------------------------------------------------------
#define ASTRIDE 272
#define A_STAGE_B (64 * ASTRIDE)                       /* 17408 */
#define W_STAGE_B 8192
#define STAGE_B   (A_STAGE_B + W_STAGE_B)              /* 25600 */
#define OFF_STA(s) ((s) * STAGE_B)
#define OFF_STW(s) ((s) * STAGE_B + A_STAGE_B)
#define OFF_FB(b)  (3 * STAGE_B + (b) * 8192)
#define SM_TOTAL_G (3 * STAGE_B + 2 * 8192)            /* 93184 */

__global__ __launch_bounds__(256, 2) void gemm_tc_kernel(const float* __restrict__ A,
                                                         const float* __restrict__ bias,
                                                         float* __restrict__ out)
{
    extern __shared__ char smem[];
    const uint32_t sb = smem_u32(smem);
    const int tid  = threadIdx.x;
    const int lane = tid & 31;
    const int wid  = tid >> 5;
    const int warp_m = wid & 3;
    const int warp_n = wid >> 2;
    const int rowBase = blockIdx.x * 64;

    const int ar = tid >> 4;
    const int aq = tid & 15;
    const float* aPtr = A + (size_t)(rowBase + ar) * D_DIM + aq * 4;

    auto issue = [&](int i) {
        if (i < 64) {
            uint32_t ab = sb + OFF_STA(i % 3);
            const float* ag = aPtr + i * 64;
#pragma unroll
            for (int p = 0; p < 4; p++)
                cp_async16(ab + (uint32_t)(ar + 16 * p) * ASTRIDE + aq * 16,
                           ag + (size_t)16 * p * D_DIM);
            uint32_t wb = sb + OFF_STW(i % 3);
            const unsigned char* wg = g_Wsw + (size_t)i * 8192 + tid * 16;
            cp_async16(wb + tid * 16, wg);
            cp_async16(wb + 4096 + tid * 16, wg + 4096);
        }
        CP_COMMIT();
    };

    float acc[4][4];
#pragma unroll
    for (int nt = 0; nt < 4; nt++)
#pragma unroll
        for (int e = 0; e < 4; e++) acc[nt][e] = 0.f;

    const uint32_t aRow = (uint32_t)(warp_m * 16 + (lane & 15)) * 128 + (uint32_t)(lane >> 4) * 16;
    const uint32_t bRow = (uint32_t)(warp_n * 32 + ((lane >> 4) & 1) * 8 + (lane & 7)) * 128 +
                          (uint32_t)((lane >> 3) & 1) * 16;

    issue(0); issue(1); issue(2);

#pragma unroll 1
    for (int i = 0; i < 64; i++) {
        CP_WAIT2();
        __syncthreads();

        const int s = i % 3;
        {
            const char* ap = smem + OFF_STA(s);
            char* fb = smem + OFF_FB(i & 1);
#pragma unroll
            for (int p = 0; p < 4; p++) {
                int r = ar + 16 * p;
                float4 v = *(const float4*)(ap + r * ASTRIDE + aq * 16);
                __half2 h01 = __floats2half2_rn(v.x, v.y);
                __half2 h23 = __floats2half2_rn(v.z, v.w);
                *(uint2*)(fb + SW128((uint32_t)(r * 128 + aq * 8))) =
                    make_uint2(*(uint32_t*)&h01, *(uint32_t*)&h23);
            }
        }
        uint32_t bW[4][2][4];
        {
            uint32_t wb = sb + OFF_STW(s);
#pragma unroll
            for (int kk = 0; kk < 4; kk++)
#pragma unroll
                for (int pr = 0; pr < 2; pr++)
                    ldmx4(bW[kk][pr],
                          wb + SW128(bRow + (uint32_t)pr * 2048 + (uint32_t)kk * 32));
        }
        __syncthreads();

        issue(i + 3);

        const uint32_t fb = sb + OFF_FB(i & 1);
#pragma unroll
        for (int kk = 0; kk < 4; kk++) {
            uint32_t aH[4];
            ldmx4(aH, fb + SW128(aRow + (uint32_t)kk * 32));
#pragma unroll
            for (int nt = 0; nt < 4; nt++)
                mma_f16(acc[nt], aH, &bW[kk][nt >> 1][(nt & 1) * 2]);
        }
    }

    const int g  = lane >> 2;
    const int tg = lane & 3;
    int row0 = rowBase + warp_m * 16 + g;
#pragma unroll
    for (int nt = 0; nt < 4; nt++) {
        int col = warp_n * 32 + nt * 8 + tg * 2;
        if (col < C_RELn) {
            float b0 = bias[col];
            out[OUT_REL + (size_t)row0 * C_RELn + col]       = acc[nt][0] + b0;
            out[OUT_REL + (size_t)(row0 + 8) * C_RELn + col] = acc[nt][2] + b0;
        }
        if (col + 1 < C_RELn) {
            float b1 = bias[col + 1];
            out[OUT_REL + (size_t)row0 * C_RELn + col + 1]       = acc[nt][1] + b1;
            out[OUT_REL + (size_t)(row0 + 8) * C_RELn + col + 1] = acc[nt][3] + b1;
        }
    }
}

// ---------------------------------------------------------------------------
// Serial pipeline (fusion reverted); NMS at issue position 3 for ncu.
// ---------------------------------------------------------------------------
extern "C" void kernel_launch(void* const* d_in, const int* in_sizes, int n_in,
                              void* d_out, int out_size)
{
    (void)in_sizes; (void)n_in; (void)out_size;
    const float* obj_logits = (const float*)d_in[0];
    const float* vr         = (const float*)d_in[1];
    const float* boxes      = (const float*)d_in[2];
    const float* W_vr       = (const float*)d_in[3];
    const float* b_vr       = (const float*)d_in[4];
    float* out = (float*)d_out;

    cudaFuncSetAttribute(gemm_tc_kernel, cudaFuncAttributeMaxDynamicSharedMemorySize, SM_TOTAL_G);

    wsplit_kernel<<<512, 512>>>(W_vr);                               // pos 0
    softmax_copy_kernel<<<64, 256>>>(obj_logits, out);               // pos 1
    gemm_tc_kernel<<<N_RELn / 64, 256, SM_TOTAL_G>>>(vr, b_vr, out); // pos 2
    nms_kernel<<<150, 512>>>(boxes);                                 // pos 3
    argmax_kernel<<<64, 256>>>(out);                                 // pos 4
}

// round 14
// speedup vs baseline: 1.0359x; 1.0195x over previous
#include <cuda_runtime.h>
#include <cuda_fp16.h>
#include <cstdint>

#define N_OBJn 512
#define C_OBJn 151
#define N_RELn 16384
#define C_RELn 51
#define D_DIM  4096

#define OUT_PREDS  (N_OBJn * C_OBJn)          /* 77312 */
#define OUT_REL    (OUT_PREDS + N_OBJn)       /* 77824 */

// Scratch (device globals — no allocation allowed)
__device__ float g_probsT[C_OBJn * N_OBJn];   // [class][obj]
__device__ float g_maskedT[C_OBJn * N_OBJn];  // [class][obj], class 0 unused
// W as fp16, pre-swizzled per 64-col chunk tile: 64 tiles x (64 rows x 128B)
__device__ __align__(16) unsigned char g_Wsw[64 * 8192];

// ---------------------------------------------------------------------------
// helpers
// ---------------------------------------------------------------------------
__device__ __forceinline__ uint32_t smem_u32(const void* p) {
    uint32_t a;
    asm("{ .reg .u64 t; cvta.to.shared.u64 t, %1; cvt.u32.u64 %0, t; }" : "=r"(a) : "l"(p));
    return a;
}
#define SW128(o) ((o) ^ (((o) >> 3) & 0x70))

__device__ __forceinline__ void cp_async16(uint32_t dst, const void* src) {
    asm volatile("cp.async.cg.shared.global [%0], [%1], 16;" :: "r"(dst), "l"(src));
}
#define CP_COMMIT() asm volatile("cp.async.commit_group;")
#define CP_WAIT2()  asm volatile("cp.async.wait_group 2;")

__device__ __forceinline__ void ldmx4(uint32_t* r, uint32_t addr) {
    asm volatile("ldmatrix.sync.aligned.m8n8.x4.shared.b16 {%0,%1,%2,%3}, [%4];"
                 : "=r"(r[0]), "=r"(r[1]), "=r"(r[2]), "=r"(r[3]) : "r"(addr));
}
__device__ __forceinline__ void mma_f16(float* d, const uint32_t* a, const uint32_t* b) {
    asm volatile(
        "mma.sync.aligned.m16n8k16.row.col.f32.f16.f16.f32 "
        "{%0,%1,%2,%3},{%4,%5,%6,%7},{%8,%9},{%0,%1,%2,%3};"
        : "+f"(d[0]), "+f"(d[1]), "+f"(d[2]), "+f"(d[3])
        : "r"(a[0]), "r"(a[1]), "r"(a[2]), "r"(a[3]), "r"(b[0]), "r"(b[1]));
}

// Exact IoU>0.3 predicate, division-free fast path (proven r9, byte-identical).
__device__ __forceinline__ bool iou_gt(float inter, float den) {
    float t    = __fmul_rn(0.3f, den);
    float diff = __fsub_rn(inter, t);
    bool pred  = diff > 0.0f;
    if (fabsf(diff) < __fmul_rn(t, 4e-7f))
        pred = __fdiv_rn(inter, den) > 0.3f;
    return pred;
}

__device__ __forceinline__ float iou_inter(const float4& a, const float4& b) {
    float xx1 = fmaxf(a.x, b.x);
    float yy1 = fmaxf(a.y, b.y);
    float xx2 = fminf(a.z, b.z);
    float yy2 = fminf(a.w, b.w);
    float wd = fmaxf(__fadd_rn(__fsub_rn(xx2, xx1), 1.0f), 0.0f);
    float ht = fmaxf(__fadd_rn(__fsub_rn(yy2, yy1), 1.0f), 0.0f);
    return __fmul_rn(wd, ht);
}

// ---------------------------------------------------------------------------
// Kernel 1: row softmax (one warp per row) + copy logits to out[0:77312)
// ---------------------------------------------------------------------------
__global__ void softmax_copy_kernel(const float* __restrict__ logits,
                                    float* __restrict__ out)
{
    int warp = threadIdx.x >> 5;
    int lane = threadIdx.x & 31;
    int row  = blockIdx.x * 8 + warp;
    if (row >= N_OBJn) return;

    float v[5];
    float mx = -1e30f;
#pragma unroll
    for (int s = 0; s < 5; s++) {
        int c = lane + 32 * s;
        v[s] = (c < C_OBJn) ? logits[row * C_OBJn + c] : -1e30f;
        mx = fmaxf(mx, v[s]);
    }
#pragma unroll
    for (int o = 16; o; o >>= 1) mx = fmaxf(mx, __shfl_xor_sync(0xffffffffu, mx, o));

    float e[5];
    float sum = 0.f;
#pragma unroll
    for (int s = 0; s < 5; s++) {
        int c = lane + 32 * s;
        e[s] = (c < C_OBJn) ? expf(v[s] - mx) : 0.f;
        sum += e[s];
    }
#pragma unroll
    for (int o = 16; o; o >>= 1) sum += __shfl_xor_sync(0xffffffffu, sum, o);

#pragma unroll
    for (int s = 0; s < 5; s++) {
        int c = lane + 32 * s;
        if (c < C_OBJn) {
            g_probsT[c * N_OBJn + row] = __fdiv_rn(e[s], sum);
            out[row * C_OBJn + c] = v[s];   // obj_dists2 passthrough
        }
    }
}

// ---------------------------------------------------------------------------
// Kernel 2: per-class NMS — r9 logic (proven 49.3us) + ONE change:
// all 16 diagonal mask blocks precomputed before the greedy loop (they depend
// only on boxes => output identical). Batches the 32 ballots per warp and
// drops the loop to 1 barrier per iteration (the only cross-warp handoff is
// s_sup[w], written at iter w-1, read at iter w — covered by that barrier).
// ---------------------------------------------------------------------------
__global__ __launch_bounds__(512) void nms_kernel(const float* __restrict__ boxes)
{
    __shared__ unsigned long long s_key[512];
    __shared__ float4 s_box[512];
    __shared__ float  s_ar[512];
    __shared__ unsigned s_diag[512];       // [block*32 + row_in_block]
    __shared__ unsigned s_sup[16];
    __shared__ unsigned s_keep[16];

    const int tid  = threadIdx.x;
    const int lane = tid & 31;
    const int w    = tid >> 5;              // 16 warps
    const int cls  = blockIdx.x + 1;

    {
        unsigned sbits = __float_as_uint(g_probsT[cls * N_OBJn + tid]);  // >= 0
        s_key[tid] = ((unsigned long long)(~sbits) << 32) | (unsigned)tid;
    }
    if (tid < 16) s_sup[tid] = 0u;
    __syncthreads();

    // Ascending bitonic sort of 512 u64 keys  == score desc, idx asc (r9)
    for (int k = 2; k <= 512; k <<= 1) {
        for (int j = k >> 1; j > 0; j >>= 1) {
            int ixj = tid ^ j;
            if (ixj > tid) {
                unsigned long long a = s_key[tid], b = s_key[ixj];
                bool up = ((tid & k) == 0);
                if ((a > b) == up) { s_key[tid] = b; s_key[ixj] = a; }
            }
            __syncthreads();
        }
    }

    // Load boxes in sorted order; own column box stays in registers
    float4 cb;
    float  ca;
    {
        int o = (int)(s_key[tid] & 0x1FFu);
        cb = *(const float4*)&boxes[(o * C_OBJn + cls) * 4];
        ca = __fmul_rn(__fadd_rn(__fsub_rn(cb.z, cb.x), 1.0f),
                       __fadd_rn(__fsub_rn(cb.w, cb.y), 1.0f));
        s_box[tid] = cb;
        s_ar[tid]  = ca;
    }
    __syncthreads();

    // Precompute ALL diagonal blocks: warp w handles rows 2w,2w+1 of every B.
#pragma unroll 1
    for (int B = 0; B < 16; B++) {
        float4 db = s_box[(B << 5) + lane];
        float  da = s_ar[(B << 5) + lane];
#pragma unroll
        for (int rr = 0; rr < 2; rr++) {
            int r = (B << 5) + (w << 1) + rr;
            float4 rb = s_box[r];
            float  ra = s_ar[r];
            float inter = iou_inter(rb, db);
            float den = __fsub_rn(__fadd_rn(ra, da), inter);
            unsigned m = __ballot_sync(0xffffffffu, iou_gt(inter, den));
            if (lane == 0) s_diag[(B << 5) + (w << 1) + rr] = m;
        }
    }
    __syncthreads();

    unsigned supbit = 0;   // this thread's column suppressed-so-far flag

#pragma unroll 1
    for (int B = 0; B < 16; B++) {
        // keep-chain, redundant per warp (pure ALU, fully unrolled)
        unsigned cur = s_sup[B];
        unsigned kb  = 0;
#pragma unroll
        for (int t = 0; t < 32; t++) {
            unsigned mi   = s_diag[(B << 5) + t];
            unsigned keep = ((cur >> t) & 1u) ^ 1u;
            kb  |= keep << t;
            cur |= keep ? mi : 0u;
        }
        if (tid == 0) s_keep[B] = kb;

        // kept rows of block B suppress future columns (w > B), early-exit
        if (w > B) {
            if (!supbit) {
                unsigned bits = kb;
                while (bits) {
                    int t = __ffs(bits) - 1;
                    bits &= bits - 1;
                    int i = (B << 5) + t;
                    float4 ib = s_box[i];         // warp-uniform broadcast
                    float  ia = s_ar[i];
                    float inter = iou_inter(ib, cb);
                    float den = __fsub_rn(__fadd_rn(ia, ca), inter);
                    if (iou_gt(inter, den)) { supbit = 1u; break; }
                }
            }
            unsigned m = __ballot_sync(0xffffffffu, supbit);
            if (lane == 0 && B == w - 1) s_sup[w] = m;
        }
        __syncthreads();
    }

    {
        unsigned kb = s_keep[w];
        bool keep = (kb >> lane) & 1u;
        int o = (int)(s_key[tid] & 0x1FFu);
        float sc = __uint_as_float(~(unsigned)(s_key[tid] >> 32));
        g_maskedT[cls * N_OBJn + o] = keep ? sc : 0.0f;
    }
}

// ---------------------------------------------------------------------------
// Kernel 3: argmax, one WARP per object (first-max tie: smaller class wins)
// ---------------------------------------------------------------------------
__global__ void argmax_kernel(float* __restrict__ out)
{
    int wid  = threadIdx.x >> 5;
    int lane = threadIdx.x & 31;
    int obj  = blockIdx.x * 8 + wid;
    if (obj >= N_OBJn) return;

    float bv = -1.0f;
    int   bc = 1000;
#pragma unroll
    for (int s = 0; s < 5; s++) {
        int c = 1 + lane + 32 * s;
        if (c < C_OBJn) {
            float v = g_maskedT[c * N_OBJn + obj];
            if (v > bv || (v == bv && c < bc)) { bv = v; bc = c; }
        }
    }
#pragma unroll
    for (int o = 16; o; o >>= 1) {
        float ov = __shfl_xor_sync(0xffffffffu, bv, o);
        int   oc = __shfl_xor_sync(0xffffffffu, bc, o);
        if (ov > bv || (ov == bv && oc < bc)) { bv = ov; bc = oc; }
    }
    if (lane == 0) out[OUT_PREDS + obj] = (float)bc;
}

// ---------------------------------------------------------------------------
// Kernel 4a: W fp32 -> fp16 pre-swizzled tiles, float4-vectorized (4 elems/thr)
// kin multiple of 4 => 8B-aligned contiguous dst (XOR with 16-multiples keeps it)
// ---------------------------------------------------------------------------
__global__ void wsplit_kernel(const float* __restrict__ W)
{
    int idx = blockIdx.x * blockDim.x + threadIdx.x;    // 0 .. 65535
    if (idx >= 64 * D_DIM / 4) return;
    int i = idx * 4;
    int n = i >> 12;
    int k = i & 4095;
    float4 x = (n < C_RELn) ? *(const float4*)&W[i]
                            : make_float4(0.f, 0.f, 0.f, 0.f);
    __half2 h01 = __floats2half2_rn(x.x, x.y);
    __half2 h23 = __floats2half2_rn(x.z, x.w);
    int chunk = k >> 6, kin = k & 63;
    uint32_t off = (uint32_t)(n * 128 + kin * 2);
    uint32_t dst = (uint32_t)chunk * 8192u + (off ^ ((uint32_t)(n & 7) * 16u));
    *(uint2*)(g_Wsw + dst) = make_uint2(*(uint32_t*)&h01, *(uint32_t*)&h23);
}

// ---------------------------------------------------------------------------
// Kernel 4b: fp16 GEMM, 3-stage cp.async pipeline (UNCHANGED from r11: 66us)
// ---------------------------------------------------------------------------
#define ASTRIDE 272
#define A_STAGE_B (64 * ASTRIDE)                       /* 17408 */
#define W_STAGE_B 8192
#define STAGE_B   (A_STAGE_B + W_STAGE_B)              /* 25600 */
#define OFF_STA(s) ((s) * STAGE_B)
#define OFF_STW(s) ((s) * STAGE_B + A_STAGE_B)
#define OFF_FB(b)  (3 * STAGE_B + (b) * 8192)
#define SM_TOTAL_G (3 * STAGE_B + 2 * 8192)            /* 93184 */

__global__ __launch_bounds__(256, 2) void gemm_tc_kernel(const float* __restrict__ A,
                                                         const float* __restrict__ bias,
                                                         float* __restrict__ out)
{
    extern __shared__ char smem[];
    const uint32_t sb = smem_u32(smem);
    const int tid  = threadIdx.x;
    const int lane = tid & 31;
    const int wid  = tid >> 5;
    const int warp_m = wid & 3;
    const int warp_n = wid >> 2;
    const int rowBase = blockIdx.x * 64;

    const int ar = tid >> 4;
    const int aq = tid & 15;
    const float* aPtr = A + (size_t)(rowBase + ar) * D_DIM + aq * 4;

    auto issue = [&](int i) {
        if (i < 64) {
            uint32_t ab = sb + OFF_STA(i % 3);
            const float* ag = aPtr + i * 64;
#pragma unroll
            for (int p = 0; p < 4; p++)
                cp_async16(ab + (uint32_t)(ar + 16 * p) * ASTRIDE + aq * 16,
                           ag + (size_t)16 * p * D_DIM);
            uint32_t wb = sb + OFF_STW(i % 3);
            const unsigned char* wg = g_Wsw + (size_t)i * 8192 + tid * 16;
            cp_async16(wb + tid * 16, wg);
            cp_async16(wb + 4096 + tid * 16, wg + 4096);
        }
        CP_COMMIT();
    };

    float acc[4][4];
#pragma unroll
    for (int nt = 0; nt < 4; nt++)
#pragma unroll
        for (int e = 0; e < 4; e++) acc[nt][e] = 0.f;

    const uint32_t aRow = (uint32_t)(warp_m * 16 + (lane & 15)) * 128 + (uint32_t)(lane >> 4) * 16;
    const uint32_t bRow = (uint32_t)(warp_n * 32 + ((lane >> 4) & 1) * 8 + (lane & 7)) * 128 +
                          (uint32_t)((lane >> 3) & 1) * 16;

    issue(0); issue(1); issue(2);

#pragma unroll 1
    for (int i = 0; i < 64; i++) {
        CP_WAIT2();
        __syncthreads();

        const int s = i % 3;
        {
            const char* ap = smem + OFF_STA(s);
            char* fb = smem + OFF_FB(i & 1);
#pragma unroll
            for (int p = 0; p < 4; p++) {
                int r = ar + 16 * p;
                float4 v = *(const float4*)(ap + r * ASTRIDE + aq * 16);
                __half2 h01 = __floats2half2_rn(v.x, v.y);
                __half2 h23 = __floats2half2_rn(v.z, v.w);
                *(uint2*)(fb + SW128((uint32_t)(r * 128 + aq * 8))) =
                    make_uint2(*(uint32_t*)&h01, *(uint32_t*)&h23);
            }
        }
        uint32_t bW[4][2][4];
        {
            uint32_t wb = sb + OFF_STW(s);
#pragma unroll
            for (int kk = 0; kk < 4; kk++)
#pragma unroll
                for (int pr = 0; pr < 2; pr++)
                    ldmx4(bW[kk][pr],
                          wb + SW128(bRow + (uint32_t)pr * 2048 + (uint32_t)kk * 32));
        }
        __syncthreads();

        issue(i + 3);

        const uint32_t fb = sb + OFF_FB(i & 1);
#pragma unroll
        for (int kk = 0; kk < 4; kk++) {
            uint32_t aH[4];
            ldmx4(aH, fb + SW128(aRow + (uint32_t)kk * 32));
#pragma unroll
            for (int nt = 0; nt < 4; nt++)
                mma_f16(acc[nt], aH, &bW[kk][nt >> 1][(nt & 1) * 2]);
        }
    }

    const int g  = lane >> 2;
    const int tg = lane & 3;
    int row0 = rowBase + warp_m * 16 + g;
#pragma unroll
    for (int nt = 0; nt < 4; nt++) {
        int col = warp_n * 32 + nt * 8 + tg * 2;
        if (col < C_RELn) {
            float b0 = bias[col];
            out[OUT_REL + (size_t)row0 * C_RELn + col]       = acc[nt][0] + b0;
            out[OUT_REL + (size_t)(row0 + 8) * C_RELn + col] = acc[nt][2] + b0;
        }
        if (col + 1 < C_RELn) {
            float b1 = bias[col + 1];
            out[OUT_REL + (size_t)row0 * C_RELn + col + 1]       = acc[nt][1] + b1;
            out[OUT_REL + (size_t)(row0 + 8) * C_RELn + col + 1] = acc[nt][3] + b1;
        }
    }
}

// ---------------------------------------------------------------------------
// Serial pipeline; NMS at issue position 3 so ncu measures the diag hoist.
// ---------------------------------------------------------------------------
extern "C" void kernel_launch(void* const* d_in, const int* in_sizes, int n_in,
                              void* d_out, int out_size)
{
    (void)in_sizes; (void)n_in; (void)out_size;
    const float* obj_logits = (const float*)d_in[0];
    const float* vr         = (const float*)d_in[1];
    const float* boxes      = (const float*)d_in[2];
    const float* W_vr       = (const float*)d_in[3];
    const float* b_vr       = (const float*)d_in[4];
    float* out = (float*)d_out;

    cudaFuncSetAttribute(gemm_tc_kernel, cudaFuncAttributeMaxDynamicSharedMemorySize, SM_TOTAL_G);

    wsplit_kernel<<<128, 512>>>(W_vr);                               // pos 0
    softmax_copy_kernel<<<64, 256>>>(obj_logits, out);               // pos 1
    gemm_tc_kernel<<<N_RELn / 64, 256, SM_TOTAL_G>>>(vr, b_vr, out); // pos 2
    nms_kernel<<<150, 512>>>(boxes);                                 // pos 3
    argmax_kernel<<<64, 256>>>(out);                                 // pos 4
}